// round 9
// baseline (speedup 1.0000x reference)
#include <cuda_runtime.h>
#include <cuda_fp16.h>

#define N_NODES 100000
#define N_EDGES 1600000
#define F_IN 48
#define N_CHUNKS 391        // ceil(100000/256)

// Scratch (device globals — no allocation allowed).
__device__ uint2  g_Yh[N_NODES * 8];   // fp16 x@W1[0] | x@W1[1] (64B/node)
__device__ uint2  g_Zh[N_NODES * 8];   // fp16 h@W2[0] | h@W2[1]
__device__ float4 g_r1[N_NODES * 4];   // x @ root1 + b1 (fp32)
__device__ float4 g_r2[N_NODES * 4];   // h @ root2 + b2 (fp32)
__device__ int    g_cnt[N_NODES];      // in-degree
__device__ int    g_off[N_NODES];      // exclusive prefix of cnt
__device__ int    g_woff[N_NODES];     // working copy for scatter positions
__device__ int    g_bsum[512];         // chunk sums for scan
__device__ unsigned long long g_perm[N_EDGES];  // dst-sorted (u_bits<<32 | src)
__device__ int    g_is64;              // 1 if edge_index is int64

__device__ __forceinline__ unsigned pack_h2(float lo, float hi)
{
    __half2 h = __floats2half2_rn(lo, hi);
    return *reinterpret_cast<unsigned*>(&h);
}
__device__ __forceinline__ float2 unpack_h2(unsigned u)
{
    __half2 h = *reinterpret_cast<__half2*>(&u);
    return __half22float2(h);
}

// ---------------------------------------------------------------------------
// Kernel 1: layer-1 per-node precompute (+ zero cnt; + dtype detect block 0).
// Block = 256 threads = 64 nodes x 4 feature-quads.
// ---------------------------------------------------------------------------
__global__ __launch_bounds__(256) void precompute1(
    const float* __restrict__ x,
    const float* __restrict__ W1,     // [2,48,16]
    const float* __restrict__ root1,  // [48,16]
    const float* __restrict__ b1,     // [16]
    const unsigned int* __restrict__ ei_words)
{
    __shared__ float sW0[F_IN * 16];
    __shared__ float sW1[F_IN * 16];
    __shared__ float sR [F_IN * 16];
    __shared__ float sx [64 * 49];

    int tid = threadIdx.x;

    if (blockIdx.x == 0 && tid < 32) {
        unsigned int v = 0;
        for (int i = tid; i < 2048; i += 32) v |= ei_words[2 * i + 1];
        unsigned int any = __any_sync(0xffffffffu, v != 0u);
        if (tid == 0) g_is64 = any ? 0 : 1;
    }

    for (int i = tid; i < F_IN * 16; i += 256) {
        sW0[i] = W1[i];
        sW1[i] = W1[F_IN * 16 + i];
        sR[i]  = root1[i];
    }
    int base = blockIdx.x * 64;
    for (int i = tid; i < 64 * F_IN; i += 256)
        sx[(i / F_IN) * 49 + (i % F_IN)] = x[base * F_IN + i];
    __syncthreads();

    int nl = tid >> 2;
    int q  = tid & 3;
    int node = base + nl;

    float4 bq = ((const float4*)b1)[q];
    float4 a0 = {0, 0, 0, 0}, a1 = {0, 0, 0, 0}, ar = bq;
    #pragma unroll
    for (int c = 0; c < F_IN; c++) {
        float xv = sx[nl * 49 + c];
        float4 w0 = ((const float4*)sW0)[c * 4 + q];
        float4 w1 = ((const float4*)sW1)[c * 4 + q];
        float4 wr = ((const float4*)sR )[c * 4 + q];
        a0.x = fmaf(xv, w0.x, a0.x); a0.y = fmaf(xv, w0.y, a0.y);
        a0.z = fmaf(xv, w0.z, a0.z); a0.w = fmaf(xv, w0.w, a0.w);
        a1.x = fmaf(xv, w1.x, a1.x); a1.y = fmaf(xv, w1.y, a1.y);
        a1.z = fmaf(xv, w1.z, a1.z); a1.w = fmaf(xv, w1.w, a1.w);
        ar.x = fmaf(xv, wr.x, ar.x); ar.y = fmaf(xv, wr.y, ar.y);
        ar.z = fmaf(xv, wr.z, ar.z); ar.w = fmaf(xv, wr.w, ar.w);
    }
    g_Yh[node * 8 + q]     = make_uint2(pack_h2(a0.x, a0.y), pack_h2(a0.z, a0.w));
    g_Yh[node * 8 + 4 + q] = make_uint2(pack_h2(a1.x, a1.y), pack_h2(a1.z, a1.w));
    g_r1[node * 4 + q] = ar;
    if (q == 0) g_cnt[node] = 0;
}

// ---------------------------------------------------------------------------
// Kernel 2: degree histogram. (Same validity predicate as scatter so that
// cnt[dst] == number of perm entries written for dst.)
// ---------------------------------------------------------------------------
__global__ __launch_bounds__(256) void hist(const void* __restrict__ ei_raw)
{
    int e = blockIdx.x * 256 + threadIdx.x;
    int src, dst;
    if (g_is64) {
        const long long* ei = (const long long*)ei_raw;
        src = (int)__ldg(&ei[e]);
        dst = (int)__ldg(&ei[N_EDGES + e]);
    } else {
        const int* ei = (const int*)ei_raw;
        src = __ldg(&ei[e]);
        dst = __ldg(&ei[N_EDGES + e]);
    }
    if ((unsigned)src < N_NODES && (unsigned)dst < N_NODES)
        atomicAdd(&g_cnt[dst], 1);
}

// ---------------------------------------------------------------------------
// Kernels 3a/3b/3c: exclusive scan of g_cnt -> g_off (and g_woff copy).
// ---------------------------------------------------------------------------
__global__ __launch_bounds__(256) void scan1()
{
    __shared__ int s[256];
    int b = blockIdx.x, t = threadIdx.x;
    int i = b * 256 + t;
    int v = (i < N_NODES) ? g_cnt[i] : 0;
    s[t] = v; __syncthreads();
    #pragma unroll
    for (int o = 1; o < 256; o <<= 1) {
        int x = (t >= o) ? s[t - o] : 0;
        __syncthreads();
        s[t] += x;
        __syncthreads();
    }
    if (i < N_NODES) g_off[i] = s[t] - v;   // chunk-local exclusive
    if (t == 255) g_bsum[b] = s[255];
}

__global__ __launch_bounds__(512) void scan2()
{
    __shared__ int s[512];
    int t = threadIdx.x;
    int v = (t < N_CHUNKS) ? g_bsum[t] : 0;
    s[t] = v; __syncthreads();
    #pragma unroll
    for (int o = 1; o < 512; o <<= 1) {
        int x = (t >= o) ? s[t - o] : 0;
        __syncthreads();
        s[t] += x;
        __syncthreads();
    }
    g_bsum[t] = s[t] - v;                   // exclusive chunk base
}

__global__ __launch_bounds__(256) void scan3()
{
    int i = blockIdx.x * 256 + threadIdx.x;
    if (i < N_NODES) {
        int o = g_off[i] + g_bsum[i >> 8];
        g_off[i] = o;
        g_woff[i] = o;
    }
}

// ---------------------------------------------------------------------------
// Kernel 4: scatter edges into dst-sorted permutation: (u_bits<<32 | src).
// ---------------------------------------------------------------------------
__global__ __launch_bounds__(256) void scatter(
    const void* __restrict__ ei_raw, const float* __restrict__ ea)
{
    int e = blockIdx.x * 256 + threadIdx.x;
    int src, dst;
    if (g_is64) {
        const long long* ei = (const long long*)ei_raw;
        src = (int)__ldg(&ei[e]);
        dst = (int)__ldg(&ei[N_EDGES + e]);
    } else {
        const int* ei = (const int*)ei_raw;
        src = __ldg(&ei[e]);
        dst = __ldg(&ei[N_EDGES + e]);
    }
    if ((unsigned)src >= N_NODES || (unsigned)dst >= N_NODES) return;
    float u = __ldg(&ea[e]);
    int pos = atomicAdd(&g_woff[dst], 1);
    g_perm[pos] = ((unsigned long long)__float_as_uint(u) << 32) | (unsigned)src;
}

// ---------------------------------------------------------------------------
// Gather-aggregate core: quad (4 lanes) per node walks its edge list.
// Returns acc (4 features per lane), atomic-free.
// ---------------------------------------------------------------------------
__device__ __forceinline__ float4 gather_acc(const uint2* __restrict__ Y,
                                             int node, int q)
{
    int beg = g_off[node];
    int n   = g_cnt[node];
    float4 acc = {0.f, 0.f, 0.f, 0.f};
    int k = 0;
    for (; k + 2 <= n; k += 2) {
        unsigned long long p0 = g_perm[beg + k];
        unsigned long long p1 = g_perm[beg + k + 1];
        int s0 = (int)(p0 & 0xffffffffu);
        int s1 = (int)(p1 & 0xffffffffu);
        float u0 = __uint_as_float((unsigned)(p0 >> 32));
        float u1 = __uint_as_float((unsigned)(p1 >> 32));
        if ((unsigned)s0 >= N_NODES) s0 = 0;
        if ((unsigned)s1 >= N_NODES) s1 = 0;
        uint2 ua0 = __ldg(&Y[s0 * 8 + q]);
        uint2 ub0 = __ldg(&Y[s0 * 8 + 4 + q]);
        uint2 ua1 = __ldg(&Y[s1 * 8 + q]);
        uint2 ub1 = __ldg(&Y[s1 * 8 + 4 + q]);
        float2 a01 = unpack_h2(ua0.x), a23 = unpack_h2(ua0.y);
        float2 b01 = unpack_h2(ub0.x), b23 = unpack_h2(ub0.y);
        acc.x += fmaf(u0, b01.x - a01.x, a01.x);
        acc.y += fmaf(u0, b01.y - a01.y, a01.y);
        acc.z += fmaf(u0, b23.x - a23.x, a23.x);
        acc.w += fmaf(u0, b23.y - a23.y, a23.y);
        a01 = unpack_h2(ua1.x); a23 = unpack_h2(ua1.y);
        b01 = unpack_h2(ub1.x); b23 = unpack_h2(ub1.y);
        acc.x += fmaf(u1, b01.x - a01.x, a01.x);
        acc.y += fmaf(u1, b01.y - a01.y, a01.y);
        acc.z += fmaf(u1, b23.x - a23.x, a23.x);
        acc.w += fmaf(u1, b23.y - a23.y, a23.y);
    }
    if (k < n) {
        unsigned long long p0 = g_perm[beg + k];
        int s0 = (int)(p0 & 0xffffffffu);
        float u0 = __uint_as_float((unsigned)(p0 >> 32));
        if ((unsigned)s0 >= N_NODES) s0 = 0;
        uint2 ua0 = __ldg(&Y[s0 * 8 + q]);
        uint2 ub0 = __ldg(&Y[s0 * 8 + 4 + q]);
        float2 a01 = unpack_h2(ua0.x), a23 = unpack_h2(ua0.y);
        float2 b01 = unpack_h2(ub0.x), b23 = unpack_h2(ub0.y);
        acc.x += fmaf(u0, b01.x - a01.x, a01.x);
        acc.y += fmaf(u0, b01.y - a01.y, a01.y);
        acc.z += fmaf(u0, b23.x - a23.x, a23.x);
        acc.w += fmaf(u0, b23.y - a23.y, a23.y);
    }
    return acc;
}

// ---------------------------------------------------------------------------
// Kernel 5: layer-1 aggregate (atomic-free) + mean + root + ELU fused with
// the layer-2 per-node precompute (16x16 GEMMs via intra-quad shfl).
// Block = 256 = 64 nodes x 4 quads.
// ---------------------------------------------------------------------------
__global__ __launch_bounds__(256) void agg1(
    const float* __restrict__ W2,     // [2,16,16]
    const float* __restrict__ root2,  // [16,16]
    const float* __restrict__ b2)     // [16]
{
    __shared__ float sW0[256], sW1[256], sR[256], sB[16];
    int tid = threadIdx.x;
    sW0[tid] = W2[tid];
    sW1[tid] = W2[256 + tid];
    sR [tid] = root2[tid];
    if (tid < 16) sB[tid] = b2[tid];
    __syncthreads();

    int nl = tid >> 2;
    int q  = tid & 3;
    int node = blockIdx.x * 64 + nl;
    if (node >= N_NODES) node = N_NODES - 1;   // duplicate work, identical writes

    float4 acc = gather_acc(g_Yh, node, q);

    float inv = 1.f / fmaxf((float)g_cnt[node], 1.f);
    float4 r1 = g_r1[node * 4 + q];
    float4 v;
    v.x = acc.x * inv + r1.x;  v.y = acc.y * inv + r1.y;
    v.z = acc.z * inv + r1.z;  v.w = acc.w * inv + r1.w;
    v.x = (v.x > 0.f) ? v.x : expm1f(v.x);
    v.y = (v.y > 0.f) ? v.y : expm1f(v.y);
    v.z = (v.z > 0.f) ? v.z : expm1f(v.z);
    v.w = (v.w > 0.f) ? v.w : expm1f(v.w);

    // h (16 vals/node) distributed 4/lane; GEMM via intra-quad shfl broadcast.
    float hv4[4] = {v.x, v.y, v.z, v.w};
    int lane = tid & 31;
    int qb = lane & ~3;
    float4 z0 = {0, 0, 0, 0}, z1 = {0, 0, 0, 0};
    float4 zr = make_float4(sB[q*4], sB[q*4+1], sB[q*4+2], sB[q*4+3]);
    #pragma unroll
    for (int c = 0; c < 16; c++) {
        float hv = __shfl_sync(0xffffffffu, hv4[c & 3], qb | (c >> 2), 32);
        float4 w0 = ((const float4*)sW0)[c * 4 + q];
        float4 w1 = ((const float4*)sW1)[c * 4 + q];
        float4 wr = ((const float4*)sR )[c * 4 + q];
        z0.x = fmaf(hv, w0.x, z0.x); z0.y = fmaf(hv, w0.y, z0.y);
        z0.z = fmaf(hv, w0.z, z0.z); z0.w = fmaf(hv, w0.w, z0.w);
        z1.x = fmaf(hv, w1.x, z1.x); z1.y = fmaf(hv, w1.y, z1.y);
        z1.z = fmaf(hv, w1.z, z1.z); z1.w = fmaf(hv, w1.w, z1.w);
        zr.x = fmaf(hv, wr.x, zr.x); zr.y = fmaf(hv, wr.y, zr.y);
        zr.z = fmaf(hv, wr.z, zr.z); zr.w = fmaf(hv, wr.w, zr.w);
    }
    g_Zh[node * 8 + q]     = make_uint2(pack_h2(z0.x, z0.y), pack_h2(z0.z, z0.w));
    g_Zh[node * 8 + 4 + q] = make_uint2(pack_h2(z1.x, z1.y), pack_h2(z1.z, z1.w));
    g_r2[node * 4 + q] = zr;
}

// ---------------------------------------------------------------------------
// Kernel 6: layer-2 aggregate (atomic-free) + mean + root + log_softmax.
// ---------------------------------------------------------------------------
__global__ __launch_bounds__(256) void agg2(float4* __restrict__ out)
{
    int tid = threadIdx.x;
    int nl = tid >> 2;
    int q  = tid & 3;
    int node = blockIdx.x * 64 + nl;
    if (node >= N_NODES) node = N_NODES - 1;

    float4 acc = gather_acc(g_Zh, node, q);

    float inv = 1.f / fmaxf((float)g_cnt[node], 1.f);
    float4 r2 = g_r2[node * 4 + q];
    float4 v;
    v.x = acc.x * inv + r2.x;  v.y = acc.y * inv + r2.y;
    v.z = acc.z * inv + r2.z;  v.w = acc.w * inv + r2.w;

    float mx = fmaxf(fmaxf(v.x, v.y), fmaxf(v.z, v.w));
    mx = fmaxf(mx, __shfl_xor_sync(0xffffffffu, mx, 1));
    mx = fmaxf(mx, __shfl_xor_sync(0xffffffffu, mx, 2));

    float s = expf(v.x - mx) + expf(v.y - mx) + expf(v.z - mx) + expf(v.w - mx);
    s += __shfl_xor_sync(0xffffffffu, s, 1);
    s += __shfl_xor_sync(0xffffffffu, s, 2);

    float c = mx + logf(s);
    float4 r;
    r.x = v.x - c; r.y = v.y - c; r.z = v.z - c; r.w = v.w - c;
    out[node * 4 + q] = r;
}

// ---------------------------------------------------------------------------
extern "C" void kernel_launch(void* const* d_in, const int* in_sizes, int n_in,
                              void* d_out, int out_size)
{
    const float* x     = (const float*)d_in[0];
    const float* ea    = (const float*)d_in[1];
    const void*  ei    = d_in[2];
    const float* W1    = (const float*)d_in[3];
    const float* root1 = (const float*)d_in[4];
    const float* b1    = (const float*)d_in[5];
    const float* W2    = (const float*)d_in[6];
    const float* root2 = (const float*)d_in[7];
    const float* b2    = (const float*)d_in[8];
    float4* out = (float4*)d_out;

    const int node_blocks = (N_NODES + 63) / 64;     // 1563
    const int edge_blocks = N_EDGES / 256;           // 6250

    precompute1<<<node_blocks, 256>>>(x, W1, root1, b1, (const unsigned int*)ei);
    hist<<<edge_blocks, 256>>>(ei);
    scan1<<<N_CHUNKS, 256>>>();
    scan2<<<1, 512>>>();
    scan3<<<N_CHUNKS, 256>>>();
    scatter<<<edge_blocks, 256>>>(ei, ea);
    agg1<<<node_blocks, 256>>>(W2, root2, b2);
    agg2<<<node_blocks, 256>>>(out);
}

// round 11
// speedup vs baseline: 1.1160x; 1.1160x over previous
#include <cuda_runtime.h>
#include <cuda_fp16.h>

#define N_NODES 100000
#define N_EDGES 1600000
#define F_IN 48
#define F_HID 16
#define F_OUT 16

// Scratch (device globals — no allocation allowed).
// Yh/Zh: fp16 per-node tables, interleaved per (node, quad):
//   uint4 at [node*4+q] = {a01, a23, b01, b23} for features q*4..q*4+3,
//   where a = x@W[0], b = x@W[1]. One LDG.128 per edge per quad.
__device__ uint4  g_Yh[N_NODES * 4];
__device__ uint4  g_Zh[N_NODES * 4];
__device__ float4 g_AGG[N_NODES * 4];  // fp32 accumulator (16 floats/node)
__device__ float4 g_r1[N_NODES * 4];   // x @ root1 + b1 (fp32)
__device__ float4 g_r2[N_NODES * 4];   // h @ root2 + b2 (fp32)
__device__ int    g_cnt[N_NODES];      // in-degree (same both layers)
__device__ int    g_is64;              // 1 if edge_index is int64

__device__ __forceinline__ void red_add_v4(float4* addr, float4 v)
{
    asm volatile("red.global.add.v4.f32 [%0], {%1, %2, %3, %4};"
                 :: "l"(addr), "f"(v.x), "f"(v.y), "f"(v.z), "f"(v.w)
                 : "memory");
}

__device__ __forceinline__ unsigned pack_h2(float lo, float hi)
{
    __half2 h = __floats2half2_rn(lo, hi);
    return *reinterpret_cast<unsigned*>(&h);
}
__device__ __forceinline__ float2 unpack_h2(unsigned u)
{
    __half2 h = *reinterpret_cast<__half2*>(&u);
    return __half22float2(h);
}

// ---------------------------------------------------------------------------
// Kernel 1: layer-1 per-node precompute (+ zero agg/cnt; + dtype detect in
// block 0). Block = 256 threads = 64 nodes x 4 feature-quads.
// ---------------------------------------------------------------------------
__global__ __launch_bounds__(256) void precompute1(
    const float* __restrict__ x,
    const float* __restrict__ W1,     // [2,48,16]
    const float* __restrict__ root1,  // [48,16]
    const float* __restrict__ b1,     // [16]
    const unsigned int* __restrict__ ei_words)
{
    __shared__ float sW0[F_IN * 16];
    __shared__ float sW1[F_IN * 16];
    __shared__ float sR [F_IN * 16];
    __shared__ float sx [64 * 49];       // pitch 49: conflict-free

    int tid = threadIdx.x;

    // dtype detect (block 0, warp 0): int64 node ids < 2^31 -> odd words zero
    if (blockIdx.x == 0 && tid < 32) {
        unsigned int v = 0;
        for (int i = tid; i < 2048; i += 32) v |= ei_words[2 * i + 1];
        unsigned int any = __any_sync(0xffffffffu, v != 0u);
        if (tid == 0) g_is64 = any ? 0 : 1;
    }

    for (int i = tid; i < F_IN * 16; i += 256) {
        sW0[i] = W1[i];
        sW1[i] = W1[F_IN * 16 + i];
        sR[i]  = root1[i];
    }
    int base = blockIdx.x * 64;
    for (int i = tid; i < 64 * F_IN; i += 256)
        sx[(i / F_IN) * 49 + (i % F_IN)] = x[base * F_IN + i];
    __syncthreads();

    int nl = tid >> 2;          // node within block (0..63)
    int q  = tid & 3;           // feature quad (0..3)
    int node = base + nl;

    float4 bq = ((const float4*)b1)[q];
    float4 a0 = {0, 0, 0, 0}, a1 = {0, 0, 0, 0}, ar = bq;
    #pragma unroll
    for (int c = 0; c < F_IN; c++) {
        float xv = sx[nl * 49 + c];
        float4 w0 = ((const float4*)sW0)[c * 4 + q];
        float4 w1 = ((const float4*)sW1)[c * 4 + q];
        float4 wr = ((const float4*)sR )[c * 4 + q];
        a0.x = fmaf(xv, w0.x, a0.x); a0.y = fmaf(xv, w0.y, a0.y);
        a0.z = fmaf(xv, w0.z, a0.z); a0.w = fmaf(xv, w0.w, a0.w);
        a1.x = fmaf(xv, w1.x, a1.x); a1.y = fmaf(xv, w1.y, a1.y);
        a1.z = fmaf(xv, w1.z, a1.z); a1.w = fmaf(xv, w1.w, a1.w);
        ar.x = fmaf(xv, wr.x, ar.x); ar.y = fmaf(xv, wr.y, ar.y);
        ar.z = fmaf(xv, wr.z, ar.z); ar.w = fmaf(xv, wr.w, ar.w);
    }
    g_Yh[node * 4 + q] = make_uint4(pack_h2(a0.x, a0.y), pack_h2(a0.z, a0.w),
                                    pack_h2(a1.x, a1.y), pack_h2(a1.z, a1.w));
    g_r1[node * 4 + q] = ar;
    g_AGG[node * 4 + q] = make_float4(0.f, 0.f, 0.f, 0.f);
    if (q == 0) g_cnt[node] = 0;
}

// ---------------------------------------------------------------------------
// Kernel 2/4: edge scatter. Each 4-lane quad handles TWO consecutive edges.
// Single LDG.128 per edge per quad (interleaved a|b record), fp32 RED.v4 out.
// ---------------------------------------------------------------------------
template <int LAYER>
__global__ __launch_bounds__(256) void edge_pass(
    const void* __restrict__ ei_raw,    // [2, N_EDGES] int32 or int64
    const float* __restrict__ ea)       // [N_EDGES] (u)
{
    int idx = blockIdx.x * 256 + threadIdx.x;   // < N_EDGES*2
    int p = idx >> 2;                           // edge pair index
    int q = idx & 3;                            // feature quad
    int e0 = 2 * p;
    int e1 = 2 * p + 1;

    int src0, dst0, src1, dst1;
    if (g_is64) {
        const long long* ei = (const long long*)ei_raw;
        src0 = (int)__ldg(&ei[e0]);
        src1 = (int)__ldg(&ei[e1]);
        dst0 = (int)__ldg(&ei[N_EDGES + e0]);
        dst1 = (int)__ldg(&ei[N_EDGES + e1]);
    } else {
        const int* ei = (const int*)ei_raw;
        src0 = __ldg(&ei[e0]);
        src1 = __ldg(&ei[e1]);
        dst0 = __ldg(&ei[N_EDGES + e0]);
        dst1 = __ldg(&ei[N_EDGES + e1]);
    }
    float u0 = __ldg(&ea[e0]);
    float u1 = __ldg(&ea[e1]);

    bool ok0 = (unsigned)src0 < N_NODES && (unsigned)dst0 < N_NODES;
    bool ok1 = (unsigned)src1 < N_NODES && (unsigned)dst1 < N_NODES;

    const uint4* __restrict__ Y = LAYER ? g_Zh : g_Yh;

    if (ok0) {
        uint4 r = __ldg(&Y[src0 * 4 + q]);
        float2 a01 = unpack_h2(r.x), a23 = unpack_h2(r.y);
        float2 b01 = unpack_h2(r.z), b23 = unpack_h2(r.w);
        float4 m;
        m.x = fmaf(u0, b01.x - a01.x, a01.x);
        m.y = fmaf(u0, b01.y - a01.y, a01.y);
        m.z = fmaf(u0, b23.x - a23.x, a23.x);
        m.w = fmaf(u0, b23.y - a23.y, a23.y);
        red_add_v4(&g_AGG[dst0 * 4 + q], m);
        if (LAYER == 0 && q == 0) atomicAdd(&g_cnt[dst0], 1);
    }
    if (ok1) {
        uint4 r = __ldg(&Y[src1 * 4 + q]);
        float2 a01 = unpack_h2(r.x), a23 = unpack_h2(r.y);
        float2 b01 = unpack_h2(r.z), b23 = unpack_h2(r.w);
        float4 m;
        m.x = fmaf(u1, b01.x - a01.x, a01.x);
        m.y = fmaf(u1, b01.y - a01.y, a01.y);
        m.z = fmaf(u1, b23.x - a23.x, a23.x);
        m.w = fmaf(u1, b23.y - a23.y, a23.y);
        red_add_v4(&g_AGG[dst1 * 4 + q], m);
        if (LAYER == 0 && q == 0) atomicAdd(&g_cnt[dst1], 1);
    }
}

// ---------------------------------------------------------------------------
// Kernel 3: finalize layer 1 (mean + root + bias + ELU) fused with the
// layer-2 per-node precompute; re-zeros agg for pass 2.
// Block = 256 threads = 64 nodes x 4 quads.
// ---------------------------------------------------------------------------
__global__ __launch_bounds__(256) void mid_fused(
    const float* __restrict__ W2,     // [2,16,16]
    const float* __restrict__ root2,  // [16,16]
    const float* __restrict__ b2)     // [16]
{
    __shared__ float sW0[16 * 16];
    __shared__ float sW1[16 * 16];
    __shared__ float sR [16 * 16];
    __shared__ float sh [64 * 17];    // pitch 17: conflict-free

    int tid = threadIdx.x;
    sW0[tid] = W2[tid];
    sW1[tid] = W2[256 + tid];
    sR [tid] = root2[tid];

    int base = blockIdx.x * 64;
    int nl = tid >> 2;
    int q  = tid & 3;
    int node = base + nl;

    float cnt = fmaxf((float)g_cnt[node], 1.f);
    float inv = 1.f / cnt;
    float4 agg = g_AGG[node * 4 + q];
    float4 r1  = g_r1[node * 4 + q];
    float4 v;
    v.x = agg.x * inv + r1.x;  v.y = agg.y * inv + r1.y;
    v.z = agg.z * inv + r1.z;  v.w = agg.w * inv + r1.w;
    v.x = (v.x > 0.f) ? v.x : expm1f(v.x);
    v.y = (v.y > 0.f) ? v.y : expm1f(v.y);
    v.z = (v.z > 0.f) ? v.z : expm1f(v.z);
    v.w = (v.w > 0.f) ? v.w : expm1f(v.w);
    sh[nl * 17 + q * 4 + 0] = v.x;
    sh[nl * 17 + q * 4 + 1] = v.y;
    sh[nl * 17 + q * 4 + 2] = v.z;
    sh[nl * 17 + q * 4 + 3] = v.w;
    g_AGG[node * 4 + q] = make_float4(0.f, 0.f, 0.f, 0.f);
    __syncthreads();

    float4 bq = ((const float4*)b2)[q];
    float4 a0 = {0, 0, 0, 0}, a1 = {0, 0, 0, 0}, ar = bq;
    #pragma unroll
    for (int c = 0; c < F_HID; c++) {
        float hv = sh[nl * 17 + c];
        float4 w0 = ((const float4*)sW0)[c * 4 + q];
        float4 w1 = ((const float4*)sW1)[c * 4 + q];
        float4 wr = ((const float4*)sR )[c * 4 + q];
        a0.x = fmaf(hv, w0.x, a0.x); a0.y = fmaf(hv, w0.y, a0.y);
        a0.z = fmaf(hv, w0.z, a0.z); a0.w = fmaf(hv, w0.w, a0.w);
        a1.x = fmaf(hv, w1.x, a1.x); a1.y = fmaf(hv, w1.y, a1.y);
        a1.z = fmaf(hv, w1.z, a1.z); a1.w = fmaf(hv, w1.w, a1.w);
        ar.x = fmaf(hv, wr.x, ar.x); ar.y = fmaf(hv, wr.y, ar.y);
        ar.z = fmaf(hv, wr.z, ar.z); ar.w = fmaf(hv, wr.w, ar.w);
    }
    g_Zh[node * 4 + q] = make_uint4(pack_h2(a0.x, a0.y), pack_h2(a0.z, a0.w),
                                    pack_h2(a1.x, a1.y), pack_h2(a1.z, a1.w));
    g_r2[node * 4 + q] = ar;
}

// ---------------------------------------------------------------------------
// Kernel 5: finalize layer 2 (mean + root + bias) + log_softmax over 16.
// Thread = (node, quad); reduction = local over 4 + shfl over 2 lanes.
// ---------------------------------------------------------------------------
__global__ __launch_bounds__(256) void finalize2(float4* __restrict__ out)
{
    int idx = blockIdx.x * 256 + threadIdx.x;   // < N_NODES*4
    int node = idx >> 2;

    float cnt = fmaxf((float)g_cnt[node], 1.f);
    float inv = 1.f / cnt;
    float4 agg = g_AGG[idx];
    float4 r2  = g_r2[idx];
    float4 v;
    v.x = agg.x * inv + r2.x;  v.y = agg.y * inv + r2.y;
    v.z = agg.z * inv + r2.z;  v.w = agg.w * inv + r2.w;

    float mx = fmaxf(fmaxf(v.x, v.y), fmaxf(v.z, v.w));
    mx = fmaxf(mx, __shfl_xor_sync(0xffffffffu, mx, 1));
    mx = fmaxf(mx, __shfl_xor_sync(0xffffffffu, mx, 2));

    float s = expf(v.x - mx) + expf(v.y - mx) + expf(v.z - mx) + expf(v.w - mx);
    s += __shfl_xor_sync(0xffffffffu, s, 1);
    s += __shfl_xor_sync(0xffffffffu, s, 2);

    float c = mx + logf(s);
    float4 r;
    r.x = v.x - c; r.y = v.y - c; r.z = v.z - c; r.w = v.w - c;
    out[idx] = r;
}

// ---------------------------------------------------------------------------
extern "C" void kernel_launch(void* const* d_in, const int* in_sizes, int n_in,
                              void* d_out, int out_size)
{
    const float* x     = (const float*)d_in[0];
    const float* ea    = (const float*)d_in[1];
    const void*  ei    = d_in[2];
    const float* W1    = (const float*)d_in[3];
    const float* root1 = (const float*)d_in[4];
    const float* b1    = (const float*)d_in[5];
    const float* W2    = (const float*)d_in[6];
    const float* root2 = (const float*)d_in[7];
    const float* b2    = (const float*)d_in[8];
    float4* out = (float4*)d_out;

    const int node_blocks = (N_NODES + 63) / 64;     // 1563
    const int nq_blocks   = (N_NODES * 4 + 255) / 256;
    const int edge_blocks = (N_EDGES * 2) / 256;     // 12500

    precompute1<<<node_blocks, 256>>>(x, W1, root1, b1, (const unsigned int*)ei);
    edge_pass<0><<<edge_blocks, 256>>>(ei, ea);
    mid_fused<<<node_blocks, 256>>>(W2, root2, b2);
    edge_pass<1><<<edge_blocks, 256>>>(ei, ea);
    finalize2<<<nq_blocks, 256>>>(out);
}

// round 12
// speedup vs baseline: 1.1234x; 1.0066x over previous
#include <cuda_runtime.h>
#include <cuda_fp16.h>

#define N_NODES 100000
#define N_EDGES 1600000
#define F_IN 48
#define F_HID 16
#define F_OUT 16

// Scratch (device globals — no allocation allowed).
// Yh/Zh: fp16 per-node tables, interleaved per (node, quad):
//   uint4 at [node*4+q] = {a01, a23, b01, b23} for features q*4..q*4+3,
//   where a = x@W[0], b = x@W[1]. One LDG.128 per edge per quad.
__device__ uint4  g_Yh[N_NODES * 4];
__device__ uint4  g_Zh[N_NODES * 4];
__device__ float4 g_AGG[N_NODES * 4];  // fp32 accumulator (16 floats/node)
__device__ float4 g_r1[N_NODES * 4];   // x @ root1 + b1 (fp32)
__device__ float4 g_r2[N_NODES * 4];   // h @ root2 + b2 (fp32)
__device__ int    g_cnt[N_NODES];      // in-degree (same both layers)
__device__ int    g_is64;              // 1 if edge_index is int64

__device__ __forceinline__ void red_add_v4(float4* addr, float4 v)
{
    asm volatile("red.global.add.v4.f32 [%0], {%1, %2, %3, %4};"
                 :: "l"(addr), "f"(v.x), "f"(v.y), "f"(v.z), "f"(v.w)
                 : "memory");
}

__device__ __forceinline__ unsigned pack_h2(float lo, float hi)
{
    __half2 h = __floats2half2_rn(lo, hi);
    return *reinterpret_cast<unsigned*>(&h);
}
__device__ __forceinline__ float2 unpack_h2(unsigned u)
{
    __half2 h = *reinterpret_cast<__half2*>(&u);
    return __half22float2(h);
}

// ---------------------------------------------------------------------------
// Kernel 1: layer-1 per-node precompute (+ zero agg/cnt; + dtype detect in
// block 0). Block = 256 threads = 64 nodes x 4 feature-quads.
// ---------------------------------------------------------------------------
__global__ __launch_bounds__(256) void precompute1(
    const float* __restrict__ x,
    const float* __restrict__ W1,     // [2,48,16]
    const float* __restrict__ root1,  // [48,16]
    const float* __restrict__ b1,     // [16]
    const unsigned int* __restrict__ ei_words)
{
    __shared__ float sW0[F_IN * 16];
    __shared__ float sW1[F_IN * 16];
    __shared__ float sR [F_IN * 16];
    __shared__ float sx [64 * 49];       // pitch 49: conflict-free

    int tid = threadIdx.x;

    // dtype detect (block 0, warp 0): int64 node ids < 2^31 -> odd words zero
    if (blockIdx.x == 0 && tid < 32) {
        unsigned int v = 0;
        for (int i = tid; i < 2048; i += 32) v |= ei_words[2 * i + 1];
        unsigned int any = __any_sync(0xffffffffu, v != 0u);
        if (tid == 0) g_is64 = any ? 0 : 1;
    }

    for (int i = tid; i < F_IN * 16; i += 256) {
        sW0[i] = W1[i];
        sW1[i] = W1[F_IN * 16 + i];
        sR[i]  = root1[i];
    }
    int base = blockIdx.x * 64;
    for (int i = tid; i < 64 * F_IN; i += 256)
        sx[(i / F_IN) * 49 + (i % F_IN)] = x[base * F_IN + i];
    __syncthreads();

    int nl = tid >> 2;          // node within block (0..63)
    int q  = tid & 3;           // feature quad (0..3)
    int node = base + nl;

    float4 bq = ((const float4*)b1)[q];
    float4 a0 = {0, 0, 0, 0}, a1 = {0, 0, 0, 0}, ar = bq;
    #pragma unroll
    for (int c = 0; c < F_IN; c++) {
        float xv = sx[nl * 49 + c];
        float4 w0 = ((const float4*)sW0)[c * 4 + q];
        float4 w1 = ((const float4*)sW1)[c * 4 + q];
        float4 wr = ((const float4*)sR )[c * 4 + q];
        a0.x = fmaf(xv, w0.x, a0.x); a0.y = fmaf(xv, w0.y, a0.y);
        a0.z = fmaf(xv, w0.z, a0.z); a0.w = fmaf(xv, w0.w, a0.w);
        a1.x = fmaf(xv, w1.x, a1.x); a1.y = fmaf(xv, w1.y, a1.y);
        a1.z = fmaf(xv, w1.z, a1.z); a1.w = fmaf(xv, w1.w, a1.w);
        ar.x = fmaf(xv, wr.x, ar.x); ar.y = fmaf(xv, wr.y, ar.y);
        ar.z = fmaf(xv, wr.z, ar.z); ar.w = fmaf(xv, wr.w, ar.w);
    }
    g_Yh[node * 4 + q] = make_uint4(pack_h2(a0.x, a0.y), pack_h2(a0.z, a0.w),
                                    pack_h2(a1.x, a1.y), pack_h2(a1.z, a1.w));
    g_r1[node * 4 + q] = ar;
    g_AGG[node * 4 + q] = make_float4(0.f, 0.f, 0.f, 0.f);
    if (q == 0) g_cnt[node] = 0;
}

// ---------------------------------------------------------------------------
// Kernel 2/4: edge scatter. Each 4-lane quad handles FOUR consecutive edges
// (deep MLP: 4 independent index loads + 4 gathers in flight). Per edge:
// one LDG.128 gather (interleaved a|b record) + one fp32 RED.v4.
// ---------------------------------------------------------------------------
template <int LAYER>
__global__ __launch_bounds__(256) void edge_pass(
    const void* __restrict__ ei_raw,    // [2, N_EDGES] int32 or int64
    const float* __restrict__ ea)       // [N_EDGES] (u)
{
    int idx = blockIdx.x * 256 + threadIdx.x;   // < N_EDGES
    int g = idx >> 2;                           // edge group (4 edges)
    int q = idx & 3;                            // feature quad
    int e = 4 * g;

    int src[4], dst[4];
    if (g_is64) {
        const long long* ei = (const long long*)ei_raw;
        #pragma unroll
        for (int k = 0; k < 4; k++) {
            src[k] = (int)__ldg(&ei[e + k]);
            dst[k] = (int)__ldg(&ei[N_EDGES + e + k]);
        }
    } else {
        const int* ei = (const int*)ei_raw;
        #pragma unroll
        for (int k = 0; k < 4; k++) {
            src[k] = __ldg(&ei[e + k]);
            dst[k] = __ldg(&ei[N_EDGES + e + k]);
        }
    }
    float u[4];
    #pragma unroll
    for (int k = 0; k < 4; k++) u[k] = __ldg(&ea[e + k]);

    const uint4* __restrict__ Y = LAYER ? g_Zh : g_Yh;

    // Issue all gathers first (max MLP), then math + REDs.
    uint4 r[4];
    bool ok[4];
    #pragma unroll
    for (int k = 0; k < 4; k++) {
        ok[k] = (unsigned)src[k] < N_NODES && (unsigned)dst[k] < N_NODES;
        int s = ok[k] ? src[k] : 0;
        r[k] = __ldg(&Y[s * 4 + q]);
    }

    #pragma unroll
    for (int k = 0; k < 4; k++) {
        if (!ok[k]) continue;
        float2 a01 = unpack_h2(r[k].x), a23 = unpack_h2(r[k].y);
        float2 b01 = unpack_h2(r[k].z), b23 = unpack_h2(r[k].w);
        float4 m;
        m.x = fmaf(u[k], b01.x - a01.x, a01.x);
        m.y = fmaf(u[k], b01.y - a01.y, a01.y);
        m.z = fmaf(u[k], b23.x - a23.x, a23.x);
        m.w = fmaf(u[k], b23.y - a23.y, a23.y);
        red_add_v4(&g_AGG[dst[k] * 4 + q], m);
        if (LAYER == 0 && q == 0) atomicAdd(&g_cnt[dst[k]], 1);
    }
}

// ---------------------------------------------------------------------------
// Kernel 3: finalize layer 1 (mean + root + bias + ELU) fused with the
// layer-2 per-node precompute; re-zeros agg for pass 2.
// Block = 256 threads = 64 nodes x 4 quads.
// ---------------------------------------------------------------------------
__global__ __launch_bounds__(256) void mid_fused(
    const float* __restrict__ W2,     // [2,16,16]
    const float* __restrict__ root2,  // [16,16]
    const float* __restrict__ b2)     // [16]
{
    __shared__ float sW0[16 * 16];
    __shared__ float sW1[16 * 16];
    __shared__ float sR [16 * 16];
    __shared__ float sh [64 * 17];    // pitch 17: conflict-free

    int tid = threadIdx.x;
    sW0[tid] = W2[tid];
    sW1[tid] = W2[256 + tid];
    sR [tid] = root2[tid];

    int base = blockIdx.x * 64;
    int nl = tid >> 2;
    int q  = tid & 3;
    int node = base + nl;

    float cnt = fmaxf((float)g_cnt[node], 1.f);
    float inv = 1.f / cnt;
    float4 agg = g_AGG[node * 4 + q];
    float4 r1  = g_r1[node * 4 + q];
    float4 v;
    v.x = agg.x * inv + r1.x;  v.y = agg.y * inv + r1.y;
    v.z = agg.z * inv + r1.z;  v.w = agg.w * inv + r1.w;
    v.x = (v.x > 0.f) ? v.x : expm1f(v.x);
    v.y = (v.y > 0.f) ? v.y : expm1f(v.y);
    v.z = (v.z > 0.f) ? v.z : expm1f(v.z);
    v.w = (v.w > 0.f) ? v.w : expm1f(v.w);
    sh[nl * 17 + q * 4 + 0] = v.x;
    sh[nl * 17 + q * 4 + 1] = v.y;
    sh[nl * 17 + q * 4 + 2] = v.z;
    sh[nl * 17 + q * 4 + 3] = v.w;
    g_AGG[node * 4 + q] = make_float4(0.f, 0.f, 0.f, 0.f);
    __syncthreads();

    float4 bq = ((const float4*)b2)[q];
    float4 a0 = {0, 0, 0, 0}, a1 = {0, 0, 0, 0}, ar = bq;
    #pragma unroll
    for (int c = 0; c < F_HID; c++) {
        float hv = sh[nl * 17 + c];
        float4 w0 = ((const float4*)sW0)[c * 4 + q];
        float4 w1 = ((const float4*)sW1)[c * 4 + q];
        float4 wr = ((const float4*)sR )[c * 4 + q];
        a0.x = fmaf(hv, w0.x, a0.x); a0.y = fmaf(hv, w0.y, a0.y);
        a0.z = fmaf(hv, w0.z, a0.z); a0.w = fmaf(hv, w0.w, a0.w);
        a1.x = fmaf(hv, w1.x, a1.x); a1.y = fmaf(hv, w1.y, a1.y);
        a1.z = fmaf(hv, w1.z, a1.z); a1.w = fmaf(hv, w1.w, a1.w);
        ar.x = fmaf(hv, wr.x, ar.x); ar.y = fmaf(hv, wr.y, ar.y);
        ar.z = fmaf(hv, wr.z, ar.z); ar.w = fmaf(hv, wr.w, ar.w);
    }
    g_Zh[node * 4 + q] = make_uint4(pack_h2(a0.x, a0.y), pack_h2(a0.z, a0.w),
                                    pack_h2(a1.x, a1.y), pack_h2(a1.z, a1.w));
    g_r2[node * 4 + q] = ar;
}

// ---------------------------------------------------------------------------
// Kernel 5: finalize layer 2 (mean + root + bias) + log_softmax over 16.
// Thread = (node, quad); reduction = local over 4 + shfl over 2 lanes.
// ---------------------------------------------------------------------------
__global__ __launch_bounds__(256) void finalize2(float4* __restrict__ out)
{
    int idx = blockIdx.x * 256 + threadIdx.x;   // < N_NODES*4
    int node = idx >> 2;

    float cnt = fmaxf((float)g_cnt[node], 1.f);
    float inv = 1.f / cnt;
    float4 agg = g_AGG[idx];
    float4 r2  = g_r2[idx];
    float4 v;
    v.x = agg.x * inv + r2.x;  v.y = agg.y * inv + r2.y;
    v.z = agg.z * inv + r2.z;  v.w = agg.w * inv + r2.w;

    float mx = fmaxf(fmaxf(v.x, v.y), fmaxf(v.z, v.w));
    mx = fmaxf(mx, __shfl_xor_sync(0xffffffffu, mx, 1));
    mx = fmaxf(mx, __shfl_xor_sync(0xffffffffu, mx, 2));

    float s = expf(v.x - mx) + expf(v.y - mx) + expf(v.z - mx) + expf(v.w - mx);
    s += __shfl_xor_sync(0xffffffffu, s, 1);
    s += __shfl_xor_sync(0xffffffffu, s, 2);

    float c = mx + logf(s);
    float4 r;
    r.x = v.x - c; r.y = v.y - c; r.z = v.z - c; r.w = v.w - c;
    out[idx] = r;
}

// ---------------------------------------------------------------------------
extern "C" void kernel_launch(void* const* d_in, const int* in_sizes, int n_in,
                              void* d_out, int out_size)
{
    const float* x     = (const float*)d_in[0];
    const float* ea    = (const float*)d_in[1];
    const void*  ei    = d_in[2];
    const float* W1    = (const float*)d_in[3];
    const float* root1 = (const float*)d_in[4];
    const float* b1    = (const float*)d_in[5];
    const float* W2    = (const float*)d_in[6];
    const float* root2 = (const float*)d_in[7];
    const float* b2    = (const float*)d_in[8];
    float4* out = (float4*)d_out;

    const int node_blocks = (N_NODES + 63) / 64;     // 1563
    const int nq_blocks   = (N_NODES * 4 + 255) / 256;
    const int edge_blocks = N_EDGES / 256;           // 6250 (1 thread : 1 edge-quad-slot)

    precompute1<<<node_blocks, 256>>>(x, W1, root1, b1, (const unsigned int*)ei);
    edge_pass<0><<<edge_blocks, 256>>>(ei, ea);
    mid_fused<<<node_blocks, 256>>>(W2, root2, b2);
    edge_pass<1><<<edge_blocks, 256>>>(ei, ea);
    finalize2<<<nq_blocks, 256>>>(out);
}